// round 15
// baseline (speedup 1.0000x reference)
#include <cuda_runtime.h>
#include <cuda_fp16.h>
#include <cstdint>

#define D 256
#define P 8
#define B_GR 128
#define N_NODES 50000
#define N_EDGES 300000
#define NHB 148
#define MAX_TILES 3072
#define KC 32
#define NCHUNK 8
#define W_CHUNK_ELEMS (256 * KC)   // 8192 fp16 per chunk (per hi or lo)
#define WSP_HALF (129 * NCHUNK * W_CHUNK_ELEMS)

// dynamic smem byte offsets (per CTA, half-tile: N=128)
#define OFF_INSTR 0
#define OFF_WVEC 1024
#define OFF_RED 2048                // 128 rows x 4 floats
#define OFF_A 4096                  // 2 buf x (hi,lo) x 128 rows x 80B
#define A_BUF_BYTES 20480           // hi+lo for one buffer
#define A_HL_BYTES 10240
#define OFF_W 45056                 // 3 buf x (hi,lo) x 128 n x 80B
#define W_BUF_BYTES 20480
#define W_HL_BYTES 10240
#define SMEM_NEED 106496

#define NTHR 320                    // 8 consumer warps + 2 producer warps
#define ZBLK ((N_NODES + 255) / 256)
#define WSBLK (D * D / 256)

// ---------------- device globals ----------------
__device__ __align__(256) __half g_Wsp[2 * WSP_HALF]; // [hi/lo][widx][chunk][n=256][k=32]
__device__ float g_state_logits[N_NODES];
__device__ float g_rel_logits[N_NODES];
__device__ int g_eperm[N_EDGES];
__device__ int g_edst[N_EDGES];
__device__ float g_ecoef[N_EDGES];
__device__ int g_binstart[B_GR + 1];
__device__ int g_blockhist[NHB * B_GR];
__device__ int g_blockbase[NHB * B_GR];
__device__ int4 g_tiles[MAX_TILES]; // {widx, b, start, cnt}
__device__ int g_ntiles;

// ---------------- helpers ----------------
__device__ __forceinline__ uint32_t smem_u32(const void* p) {
    uint32_t a;
    asm("{ .reg .u64 t; cvta.to.shared.u64 t, %1; cvt.u32.u64 %0, t; }" : "=r"(a) : "l"(p));
    return a;
}
__device__ __forceinline__ void ldsm4(uint32_t* r, uint32_t addr) {
    asm volatile("ldmatrix.sync.aligned.m8n8.x4.shared.b16 {%0,%1,%2,%3}, [%4];"
                 : "=r"(r[0]), "=r"(r[1]), "=r"(r[2]), "=r"(r[3]) : "r"(addr));
}
__device__ __forceinline__ void mma16816(float* c, const uint32_t* a, uint32_t b0, uint32_t b1) {
    asm volatile(
        "mma.sync.aligned.m16n8k16.row.col.f32.f16.f16.f32 "
        "{%0,%1,%2,%3}, {%4,%5,%6,%7}, {%8,%9}, {%0,%1,%2,%3};"
        : "+f"(c[0]), "+f"(c[1]), "+f"(c[2]), "+f"(c[3])
        : "r"(a[0]), "r"(a[1]), "r"(a[2]), "r"(a[3]), "r"(b0), "r"(b1));
}
__device__ __forceinline__ void cpasync16(uint32_t saddr, const void* gaddr) {
    asm volatile("cp.async.cg.shared.global [%0], [%1], 16;" :: "r"(saddr), "l"(gaddr) : "memory");
}
__device__ __forceinline__ void cp_commit() { asm volatile("cp.async.commit_group;" ::: "memory"); }
__device__ __forceinline__ void cp_wait_all() { asm volatile("cp.async.wait_group 0;" ::: "memory"); }
__device__ __forceinline__ void cp_wait_1() { asm volatile("cp.async.wait_group 1;" ::: "memory"); }
__device__ __forceinline__ float elu1(float x) { return x > 0.f ? x : expm1f(x); }

// ---------------- L0: hist + zero ----------------
__global__ void __launch_bounds__(256) l0_kernel(const int* __restrict__ eb) {
    int blk = blockIdx.x;
    int t = threadIdx.x;
    if (blk < NHB) {
        __shared__ int h[B_GR];
        if (t < B_GR) h[t] = 0;
        __syncthreads();
        for (int e = blk * 256 + t; e < N_EDGES; e += NHB * 256)
            atomicAdd(&h[eb[e]], 1);
        __syncthreads();
        if (t < B_GR) g_blockhist[blk * B_GR + t] = h[t];
    } else {
        int i = (blk - NHB) * 256 + t;
        if (i < N_NODES) { g_rel_logits[i] = 0.f; g_state_logits[i] = 0.f; }
    }
}

// ---------------- L1: scan ----------------
__global__ void scan_kernel() {
    __shared__ int tot[B_GR];
    __shared__ int starts[B_GR + 1];
    int b = threadIdx.x;  // 128 threads
    int s = 0;
    for (int blk = 0; blk < NHB; blk++) s += g_blockhist[blk * B_GR + b];
    tot[b] = s;
    __syncthreads();
    if (b == 0) {
        int run = 0;
        for (int i = 0; i < B_GR; i++) { starts[i] = run; run += tot[i]; }
        starts[B_GR] = run;
        for (int i = 0; i <= B_GR; i++) g_binstart[i] = starts[i];
    }
    __syncthreads();
    {
        int run = starts[b];
        for (int blk = 0; blk < NHB; blk++) {
            g_blockbase[blk * B_GR + b] = run;
            run += g_blockhist[blk * B_GR + b];
        }
    }
}

// fp32 -> (hi,lo) fp16, chunk-blocked [widx][chunk][n][k32]
__device__ __forceinline__ void store_split(int widx, int n, int k, float v) {
    __half h = __float2half_rn(v);
    __half l = __float2half_rn(v - __half2float(h));
    int chunk = k >> 5, kk = k & 31;
    size_t idx = ((size_t)(widx * NCHUNK + chunk) * 256 + n) * 32 + kk;
    g_Wsp[idx] = h;
    g_Wsp[idx + WSP_HALF] = l;
}

__device__ __forceinline__ int lower_bound_dev(const int* __restrict__ a, int n, int key) {
    int lo = 0, hi = n;
    while (lo < hi) {
        int mid = (lo + hi) >> 1;
        if (a[mid] < key) lo = mid + 1; else hi = mid;
    }
    return lo;
}

// ---------------- L2: scatter + wsplit + plan ----------------
__global__ void __launch_bounds__(256) l2_kernel(const int* __restrict__ eb,
                                                 const int* __restrict__ src,
                                                 const int* __restrict__ dst,
                                                 const float* __restrict__ dist,
                                                 const float* __restrict__ Wnp,
                                                 const float* __restrict__ We,
                                                 const float* __restrict__ sim,
                                                 const int* __restrict__ nidx) {
    int blk = blockIdx.x;
    int t = threadIdx.x;
    if (blk < NHB) {
        __shared__ int cur[B_GR];
        if (t < B_GR) cur[t] = g_blockbase[blk * B_GR + t];
        __syncthreads();
        for (int e = blk * 256 + t; e < N_EDGES; e += NHB * 256) {
            int b = eb[e];
            int pos = atomicAdd(&cur[b], 1);
            g_eperm[pos] = e;
            g_edst[pos] = dst[e];
            g_ecoef[pos] = dist[src[e]];
        }
    } else if (blk < NHB + WSBLK) {
        __shared__ float sim_s[B_GR * P];
        for (int i = t; i < B_GR * P; i += 256) sim_s[i] = sim[i];
        __syncthreads();
        int pos = (blk - NHB) * 256 + t;
        int n = pos >> 8, k = pos & 255;
        store_split(128, n, k, We[pos]);
        float wp[P];
#pragma unroll
        for (int p = 0; p < P; p++) wp[p] = Wnp[p * (D * D) + pos];
        for (int b = 0; b < B_GR; b++) {
            float a = 0.f;
#pragma unroll
            for (int p = 0; p < P; p++) a = fmaf(sim_s[b * P + p], wp[p], a);
            store_split(b, n, k, a);
        }
    } else {
        __shared__ int cnts[B_GR];
        __shared__ int starts[B_GR];
        __shared__ int info[B_GR][2];
        int b = t;
        if (b < B_GR) {
            int elo = g_binstart[b], ecnt = g_binstart[b + 1] - elo;
            int nlo = lower_bound_dev(nidx, N_NODES, b);
            int ncnt = lower_bound_dev(nidx, N_NODES, b + 1) - nlo;
            cnts[b] = ((ecnt + 127) >> 7) + ((ncnt + 127) >> 7);
            info[b][0] = elo;
            info[b][1] = nlo;
        }
        __syncthreads();
        if (t == 0) {
            int run = 0;
            for (int i = 0; i < B_GR; i++) { starts[i] = run; run += cnts[i]; }
            g_ntiles = run;
        }
        __syncthreads();
        if (b < B_GR) {
            int elo = info[b][0], ecnt = g_binstart[b + 1] - elo;
            int nlo = info[b][1];
            int ncnt = lower_bound_dev(nidx, N_NODES, b + 1) - nlo;
            int et = (ecnt + 127) >> 7, nt = (ncnt + 127) >> 7;
            int idx = starts[b];
            for (int k = 0; k < et; k++)
                g_tiles[idx++] = make_int4(128, b, elo + k * 128, min(128, ecnt - k * 128));
            for (int k = 0; k < nt; k++)
                g_tiles[idx++] = make_int4(b, b, nlo + k * 128, min(128, ncnt - k * 128));
        }
    }
}

// ---------------- L3: main HMMA kernel (warp-specialized producer/consumer) ----------------
// 320 threads: warps 0-7 consumers (2 m-groups x 4 n-groups, M64xN32 warp tiles),
// warps 8-9 producers (W cp.async + A load/convert/store).
__global__ void __launch_bounds__(NTHR, 2) main_kernel(const float* __restrict__ node_attrs,
                                                       const float* __restrict__ edge_attrs,
                                                       const float* __restrict__ instr,
                                                       const float* __restrict__ w_node,
                                                       const float* __restrict__ w_rel) {
    extern __shared__ char smem[];
    const int tb = blockIdx.x >> 1;
    if (tb >= g_ntiles) return;
    const int half = blockIdx.x & 1;
    const int nofs = half * 128;
    const int4 ti = g_tiles[tb];
    const bool isEdge = (ti.x == 128);
    const int tid = threadIdx.x;
    const int lane = tid & 31;
    const int wid = tid >> 5;
    const bool isProd = (wid >= 8);
    const int mbase = (wid & 1) * 64;
    const int ngrp = wid >> 1;           // consumers: 0..3

    const uint32_t sb = smem_u32(smem);
    float* instr_s = (float*)(smem + OFF_INSTR);
    float* wvec_s = (float*)(smem + OFF_WVEC);
    float* red = (float*)(smem + OFF_RED);

    if (tid < 256) {
        instr_s[tid] = instr[ti.y * D + tid];
        wvec_s[tid] = (isEdge ? w_rel : w_node)[tid];
    }

    const __half* wh = g_Wsp + (size_t)ti.x * NCHUNK * W_CHUNK_ELEMS + (size_t)nofs * 32;

    // Producer A assignment: 64 producer threads, 2 rows each
    const int ptid = tid - 256;          // 0..63 for producers
    const int prow0 = ptid * 2;

#define ISSUE_W(c, buf)                                                             \
    do {                                                                            \
        uint32_t wbb = sb + OFF_W + (buf) * W_BUF_BYTES;                            \
        const __half* whc = wh + (size_t)(c) * W_CHUNK_ELEMS;                       \
        for (int s = ptid; s < 512; s += 64) {                                      \
            int n_ = s >> 2, ks_ = s & 3;                                           \
            uint32_t d_ = wbb + n_ * 80 + ks_ * 16;                                 \
            size_t g_ = (size_t)n_ * 32 + ks_ * 8;                                  \
            cpasync16(d_, whc + g_);                                                \
            cpasync16(d_ + W_HL_BYTES, whc + WSP_HALF + g_);                        \
        }                                                                           \
        cp_commit();                                                                \
    } while (0)

// Convert+store one float4 (4 halfs hi + 4 halfs lo).
#define STS_ONE(v, ab_, off)                                                        \
    do {                                                                            \
        __half2 hA = __floats2half2_rn((v).x, (v).y);                               \
        __half2 hB = __floats2half2_rn((v).z, (v).w);                               \
        uint2 u_;                                                                   \
        u_.x = *(uint32_t*)&hA; u_.y = *(uint32_t*)&hB;                             \
        *(uint2*)((ab_) + (off)) = u_;                                              \
        __half2 lA = __floats2half2_rn((v).x - __half2float(__low2half(hA)),        \
                                       (v).y - __half2float(__high2half(hA)));     \
        __half2 lB = __floats2half2_rn((v).z - __half2float(__low2half(hB)),        \
                                       (v).w - __half2float(__high2half(hB)));     \
        u_.x = *(uint32_t*)&lA; u_.y = *(uint32_t*)&lB;                             \
        *(uint2*)((ab_) + A_HL_BYTES + (off)) = u_;                                 \
    } while (0)

#define PRODUCE_A(c, buf)                                                           \
    do {                                                                            \
        for (int rr = 0; rr < 2; rr++) {                                            \
            int row = prow0 + rr;                                                   \
            char* ab_ = smem + OFF_A + (buf) * A_BUF_BYTES + row * 80;              \
            if (row < ti.w) {                                                       \
                int srow = ti.z + row;                                              \
                const float* rp = isEdge ? edge_attrs + (size_t)g_eperm[srow] * D   \
                                         : node_attrs + (size_t)srow * D;           \
                const float4* p_ = (const float4*)(rp + (c) * KC);                  \
                float4 va = __ldg(p_), vb = __ldg(p_ + 1);                          \
                float4 vc = __ldg(p_ + 2), vd = __ldg(p_ + 3);                      \
                float4 ve = __ldg(p_ + 4), vf = __ldg(p_ + 5);                      \
                float4 vg = __ldg(p_ + 6), vhh = __ldg(p_ + 7);                     \
                STS_ONE(va, ab_, 0);  STS_ONE(vb, ab_, 8);                          \
                STS_ONE(vc, ab_, 16); STS_ONE(vd, ab_, 24);                         \
                STS_ONE(ve, ab_, 32); STS_ONE(vf, ab_, 40);                         \
                STS_ONE(vg, ab_, 48); STS_ONE(vhh, ab_, 56);                        \
            } else {                                                                \
                uint4 z_ = make_uint4(0u, 0u, 0u, 0u);                              \
                for (int q = 0; q < 4; q++) {                                       \
                    *(uint4*)(ab_ + q * 16) = z_;                                   \
                    *(uint4*)(ab_ + A_HL_BYTES + q * 16) = z_;                      \
                }                                                                   \
            }                                                                       \
        }                                                                           \
    } while (0)

    float acc[4][4][4];
#pragma unroll
    for (int a = 0; a < 4; a++)
#pragma unroll
        for (int b = 0; b < 4; b++)
#pragma unroll
            for (int c = 0; c < 4; c++) acc[a][b][c] = 0.f;

    // prologue (producers): W chunks 0,1; A chunk 0; ensure W0 done.
    if (isProd) {
        ISSUE_W(0, 0);
        ISSUE_W(1, 1);
        PRODUCE_A(0, 0);
        cp_wait_1();
    }
    __syncthreads();

#pragma unroll 1
    for (int c = 0; c < NCHUNK; c++) {
        if (isProd) {
            if (c + 2 < NCHUNK) ISSUE_W(c + 2, (c + 2) % 3);
            if (c + 1 < NCHUNK) PRODUCE_A(c + 1, (c + 1) & 1);
            if (c + 2 < NCHUNK) cp_wait_1(); else cp_wait_all();
        } else {
            const uint32_t abase = sb + OFF_A + (c & 1) * A_BUF_BYTES;
            const uint32_t wbase = sb + OFF_W + (c % 3) * W_BUF_BYTES;
            // ---- pass group 1: Ah x (Wh, Wl) ----
#pragma unroll
            for (int ks = 0; ks < 2; ks++) {
                const int k0 = ks * 16;
                uint32_t ah[4][4];
#pragma unroll
                for (int mi = 0; mi < 4; mi++) {
                    uint32_t ra = abase + (mbase + mi * 16 + (lane & 15)) * 80 + k0 * 2 +
                                  ((lane >> 4) * 16);
                    ldsm4(ah[mi], ra);
                }
#pragma unroll
                for (int nip = 0; nip < 2; nip++) {
                    const int nloc = ngrp * 32 + nip * 16;
                    uint32_t rb = wbase + (nloc + ((lane >> 4) << 3) + (lane & 7)) * 80 + k0 * 2 +
                                  (((lane >> 3) & 1) * 16);
                    uint32_t bh[4], bl[4];
                    ldsm4(bh, rb);
                    ldsm4(bl, rb + W_HL_BYTES);
#pragma unroll
                    for (int mi = 0; mi < 4; mi++) {
                        mma16816(acc[mi][nip * 2 + 0], ah[mi], bh[0], bh[1]);
                        mma16816(acc[mi][nip * 2 + 1], ah[mi], bh[2], bh[3]);
                        mma16816(acc[mi][nip * 2 + 0], ah[mi], bl[0], bl[1]);
                        mma16816(acc[mi][nip * 2 + 1], ah[mi], bl[2], bl[3]);
                    }
                }
            }
            // ---- pass group 2: Al x Wh ----
#pragma unroll
            for (int ks = 0; ks < 2; ks++) {
                const int k0 = ks * 16;
                uint32_t al[4][4];
#pragma unroll
                for (int mi = 0; mi < 4; mi++) {
                    uint32_t ra = abase + A_HL_BYTES + (mbase + mi * 16 + (lane & 15)) * 80 +
                                  k0 * 2 + ((lane >> 4) * 16);
                    ldsm4(al[mi], ra);
                }
#pragma unroll
                for (int nip = 0; nip < 2; nip++) {
                    const int nloc = ngrp * 32 + nip * 16;
                    uint32_t rb = wbase + (nloc + ((lane >> 4) << 3) + (lane & 7)) * 80 + k0 * 2 +
                                  (((lane >> 3) & 1) * 16);
                    uint32_t bh[4];
                    ldsm4(bh, rb);
#pragma unroll
                    for (int mi = 0; mi < 4; mi++) {
                        mma16816(acc[mi][0 + nip * 2], al[mi], bh[0], bh[1]);
                        mma16816(acc[mi][1 + nip * 2], al[mi], bh[2], bh[3]);
                    }
                }
            }
        }
        __syncthreads();
    }

    // ---- epilogue: per-row partial over this half's 128 columns ----
    if (!isProd) {
#pragma unroll
        for (int mi = 0; mi < 4; mi++) {
            float pr0 = 0.f, pr1 = 0.f;
#pragma unroll
            for (int ni = 0; ni < 4; ni++) {
                int c0 = nofs + ngrp * 32 + (ni >> 1) * 16 + (ni & 1) * 8 + (lane & 3) * 2;
                float w0 = wvec_s[c0], w1 = wvec_s[c0 + 1];
                float i0 = instr_s[c0], i1 = instr_s[c0 + 1];
                pr0 += w0 * elu1(i0 * acc[mi][ni][0]) + w1 * elu1(i1 * acc[mi][ni][1]);
                pr1 += w0 * elu1(i0 * acc[mi][ni][2]) + w1 * elu1(i1 * acc[mi][ni][3]);
            }
            pr0 += __shfl_xor_sync(0xFFFFFFFFu, pr0, 1);
            pr0 += __shfl_xor_sync(0xFFFFFFFFu, pr0, 2);
            pr1 += __shfl_xor_sync(0xFFFFFFFFu, pr1, 1);
            pr1 += __shfl_xor_sync(0xFFFFFFFFu, pr1, 2);
            if ((lane & 3) == 0) {
                int row = mbase + mi * 16 + (lane >> 2);
                red[row * 4 + ngrp] = pr0;
                red[(row + 8) * 4 + ngrp] = pr1;
            }
        }
    }
    __syncthreads();
    if (tid < 128 && tid < ti.w) {
        float v = red[tid * 4] + red[tid * 4 + 1] + red[tid * 4 + 2] + red[tid * 4 + 3];
        int gl = ti.z + tid;
        if (isEdge) atomicAdd(&g_rel_logits[g_edst[gl]], g_ecoef[gl] * v);
        else atomicAdd(&g_state_logits[gl], v);
    }
#undef ISSUE_W
#undef STS_ONE
#undef PRODUCE_A
}

// ---------------- L4: segment softmax + combine ----------------
__global__ void __launch_bounds__(256) softmax_kernel(const int* __restrict__ nidx,
                                                      const float* __restrict__ rel_sim,
                                                      float* __restrict__ out) {
    const int b = blockIdx.x;
    const int t = threadIdx.x;
    __shared__ float sh[256];
    __shared__ int bounds[2];
    if (t == 0) {
        bounds[0] = lower_bound_dev(nidx, N_NODES, b);
        bounds[1] = lower_bound_dev(nidx, N_NODES, b + 1);
    }
    __syncthreads();
    const int lo = bounds[0], hi = bounds[1];
    if (hi <= lo) return;

    float m1 = -1e30f, m2 = -1e30f;
    for (int i = lo + t; i < hi; i += 256) {
        m1 = fmaxf(m1, g_state_logits[i]);
        m2 = fmaxf(m2, g_rel_logits[i]);
    }
    sh[t] = m1; __syncthreads();
    for (int o = 128; o > 0; o >>= 1) { if (t < o) sh[t] = fmaxf(sh[t], sh[t + o]); __syncthreads(); }
    m1 = sh[0]; __syncthreads();
    sh[t] = m2; __syncthreads();
    for (int o = 128; o > 0; o >>= 1) { if (t < o) sh[t] = fmaxf(sh[t], sh[t + o]); __syncthreads(); }
    m2 = sh[0]; __syncthreads();

    float s1 = 0.f, s2 = 0.f;
    for (int i = lo + t; i < hi; i += 256) {
        s1 += expf(g_state_logits[i] - m1);
        s2 += expf(g_rel_logits[i] - m2);
    }
    sh[t] = s1; __syncthreads();
    for (int o = 128; o > 0; o >>= 1) { if (t < o) sh[t] += sh[t + o]; __syncthreads(); }
    s1 = sh[0]; __syncthreads();
    sh[t] = s2; __syncthreads();
    for (int o = 128; o > 0; o >>= 1) { if (t < o) sh[t] += sh[t + o]; __syncthreads(); }
    s2 = sh[0]; __syncthreads();

    const float r = rel_sim[b];
    const float inv1 = 1.f / s1, inv2 = 1.f / s2;
    for (int i = lo + t; i < hi; i += 256) {
        float ns = expf(g_state_logits[i] - m1) * inv1;
        float nr = expf(g_rel_logits[i] - m2) * inv2;
        out[i] = r * nr + (1.f - r) * ns;
    }
}

extern "C" void kernel_launch(void* const* d_in, const int* in_sizes, int n_in,
                              void* d_out, int out_size) {
    const float* instr        = (const float*)d_in[0];
    const float* distribution = (const float*)d_in[1];
    const float* sim          = (const float*)d_in[2];
    const float* rel_sim      = (const float*)d_in[3];
    const float* node_attrs   = (const float*)d_in[4];
    const float* edge_attrs   = (const float*)d_in[5];
    const float* Wnp          = (const float*)d_in[6];
    const float* We           = (const float*)d_in[7];
    const float* w_node       = (const float*)d_in[8];
    const float* w_rel        = (const float*)d_in[9];
    const int*   node_indices = (const int*)d_in[10];
    const int*   edge_batch   = (const int*)d_in[11];
    const int*   ei           = (const int*)d_in[12];
    float* out = (float*)d_out;

    cudaFuncSetAttribute(main_kernel, cudaFuncAttributeMaxDynamicSharedMemorySize, SMEM_NEED);

    l0_kernel<<<NHB + ZBLK, 256>>>(edge_batch);
    scan_kernel<<<1, 128>>>();
    l2_kernel<<<NHB + WSBLK + 1, 256>>>(edge_batch, ei, ei + N_EDGES, distribution,
                                        Wnp, We, sim, node_indices);
    main_kernel<<<2 * MAX_TILES, NTHR, SMEM_NEED>>>(node_attrs, edge_attrs, instr,
                                                    w_node, w_rel);
    softmax_kernel<<<B_GR, 256>>>(node_indices, rel_sim, out);
}

// round 16
// speedup vs baseline: 1.7654x; 1.7654x over previous
#include <cuda_runtime.h>
#include <cuda_fp16.h>
#include <cstdint>

#define D 256
#define P 8
#define B_GR 128
#define N_NODES 50000
#define N_EDGES 300000
#define NHB 148
#define MAX_TILES 3072
#define KC 32
#define NCHUNK 8
#define W_CHUNK_ELEMS (256 * KC)   // 8192 fp16 per chunk (per hi or lo)
#define WSP_HALF (129 * NCHUNK * W_CHUNK_ELEMS)

// dynamic smem byte offsets (per CTA, half-tile: N=128)
#define OFF_INSTR 0
#define OFF_WVEC 1024
#define OFF_RED 2048                // 128 rows x 4 floats
#define OFF_A 4096                  // 2 buf x (hi,lo) x 128 rows x 80B
#define A_BUF_BYTES 20480           // hi+lo for one buffer
#define A_HL_BYTES 10240
#define OFF_W 45056                 // 3 buf x (hi,lo) x 128 n x 80B
#define W_BUF_BYTES 20480
#define W_HL_BYTES 10240
#define SMEM_NEED 106496

#define ZBLK ((N_NODES + 255) / 256)
#define WSBLK (D * D / 256)

// ---------------- device globals ----------------
__device__ __align__(256) __half g_Wsp[2 * WSP_HALF]; // [hi/lo][widx][chunk][n=256][k=32]
__device__ float g_state_logits[N_NODES];
__device__ float g_rel_logits[N_NODES];
__device__ int g_eperm[N_EDGES];
__device__ int g_edst[N_EDGES];
__device__ float g_ecoef[N_EDGES];
__device__ int g_binstart[B_GR + 1];
__device__ int g_blockhist[NHB * B_GR];
__device__ int g_blockbase[NHB * B_GR];
__device__ int4 g_tiles[MAX_TILES]; // {widx, b, start, cnt}
__device__ int g_ntiles;

// ---------------- helpers ----------------
__device__ __forceinline__ uint32_t smem_u32(const void* p) {
    uint32_t a;
    asm("{ .reg .u64 t; cvta.to.shared.u64 t, %1; cvt.u32.u64 %0, t; }" : "=r"(a) : "l"(p));
    return a;
}
__device__ __forceinline__ void ldsm4(uint32_t* r, uint32_t addr) {
    asm volatile("ldmatrix.sync.aligned.m8n8.x4.shared.b16 {%0,%1,%2,%3}, [%4];"
                 : "=r"(r[0]), "=r"(r[1]), "=r"(r[2]), "=r"(r[3]) : "r"(addr));
}
__device__ __forceinline__ void mma16816(float* c, const uint32_t* a, uint32_t b0, uint32_t b1) {
    asm volatile(
        "mma.sync.aligned.m16n8k16.row.col.f32.f16.f16.f32 "
        "{%0,%1,%2,%3}, {%4,%5,%6,%7}, {%8,%9}, {%0,%1,%2,%3};"
        : "+f"(c[0]), "+f"(c[1]), "+f"(c[2]), "+f"(c[3])
        : "r"(a[0]), "r"(a[1]), "r"(a[2]), "r"(a[3]), "r"(b0), "r"(b1));
}
__device__ __forceinline__ void cpasync16(uint32_t saddr, const void* gaddr) {
    asm volatile("cp.async.cg.shared.global [%0], [%1], 16;" :: "r"(saddr), "l"(gaddr) : "memory");
}
__device__ __forceinline__ void cp_commit() { asm volatile("cp.async.commit_group;" ::: "memory"); }
__device__ __forceinline__ void cp_wait_all() { asm volatile("cp.async.wait_group 0;" ::: "memory"); }
__device__ __forceinline__ void cp_wait_1() { asm volatile("cp.async.wait_group 1;" ::: "memory"); }
__device__ __forceinline__ float elu1(float x) { return x > 0.f ? x : expm1f(x); }

// ---------------- L0: hist + zero ----------------
__global__ void __launch_bounds__(256) l0_kernel(const int* __restrict__ eb) {
    int blk = blockIdx.x;
    int t = threadIdx.x;
    if (blk < NHB) {
        __shared__ int h[B_GR];
        if (t < B_GR) h[t] = 0;
        __syncthreads();
        for (int e = blk * 256 + t; e < N_EDGES; e += NHB * 256)
            atomicAdd(&h[eb[e]], 1);
        __syncthreads();
        if (t < B_GR) g_blockhist[blk * B_GR + t] = h[t];
    } else {
        int i = (blk - NHB) * 256 + t;
        if (i < N_NODES) { g_rel_logits[i] = 0.f; g_state_logits[i] = 0.f; }
    }
}

// ---------------- L1: scan ----------------
__global__ void scan_kernel() {
    __shared__ int tot[B_GR];
    __shared__ int starts[B_GR + 1];
    int b = threadIdx.x;  // 128 threads
    int s = 0;
    for (int blk = 0; blk < NHB; blk++) s += g_blockhist[blk * B_GR + b];
    tot[b] = s;
    __syncthreads();
    if (b == 0) {
        int run = 0;
        for (int i = 0; i < B_GR; i++) { starts[i] = run; run += tot[i]; }
        starts[B_GR] = run;
        for (int i = 0; i <= B_GR; i++) g_binstart[i] = starts[i];
    }
    __syncthreads();
    {
        int run = starts[b];
        for (int blk = 0; blk < NHB; blk++) {
            g_blockbase[blk * B_GR + b] = run;
            run += g_blockhist[blk * B_GR + b];
        }
    }
}

// fp32 -> (hi,lo) fp16, chunk-blocked [widx][chunk][n][k32]
__device__ __forceinline__ void store_split(int widx, int n, int k, float v) {
    __half h = __float2half_rn(v);
    __half l = __float2half_rn(v - __half2float(h));
    int chunk = k >> 5, kk = k & 31;
    size_t idx = ((size_t)(widx * NCHUNK + chunk) * 256 + n) * 32 + kk;
    g_Wsp[idx] = h;
    g_Wsp[idx + WSP_HALF] = l;
}

__device__ __forceinline__ int lower_bound_dev(const int* __restrict__ a, int n, int key) {
    int lo = 0, hi = n;
    while (lo < hi) {
        int mid = (lo + hi) >> 1;
        if (a[mid] < key) lo = mid + 1; else hi = mid;
    }
    return lo;
}

// ---------------- L2: scatter + wsplit + plan ----------------
__global__ void __launch_bounds__(256) l2_kernel(const int* __restrict__ eb,
                                                 const int* __restrict__ src,
                                                 const int* __restrict__ dst,
                                                 const float* __restrict__ dist,
                                                 const float* __restrict__ Wnp,
                                                 const float* __restrict__ We,
                                                 const float* __restrict__ sim,
                                                 const int* __restrict__ nidx) {
    int blk = blockIdx.x;
    int t = threadIdx.x;
    if (blk < NHB) {
        __shared__ int cur[B_GR];
        if (t < B_GR) cur[t] = g_blockbase[blk * B_GR + t];
        __syncthreads();
        for (int e = blk * 256 + t; e < N_EDGES; e += NHB * 256) {
            int b = eb[e];
            int pos = atomicAdd(&cur[b], 1);
            g_eperm[pos] = e;
            g_edst[pos] = dst[e];
            g_ecoef[pos] = dist[src[e]];
        }
    } else if (blk < NHB + WSBLK) {
        __shared__ float sim_s[B_GR * P];
        for (int i = t; i < B_GR * P; i += 256) sim_s[i] = sim[i];
        __syncthreads();
        int pos = (blk - NHB) * 256 + t;
        int n = pos >> 8, k = pos & 255;
        store_split(128, n, k, We[pos]);
        float wp[P];
#pragma unroll
        for (int p = 0; p < P; p++) wp[p] = Wnp[p * (D * D) + pos];
        for (int b = 0; b < B_GR; b++) {
            float a = 0.f;
#pragma unroll
            for (int p = 0; p < P; p++) a = fmaf(sim_s[b * P + p], wp[p], a);
            store_split(b, n, k, a);
        }
    } else {
        __shared__ int cnts[B_GR];
        __shared__ int starts[B_GR];
        __shared__ int info[B_GR][2];
        int b = t;
        if (b < B_GR) {
            int elo = g_binstart[b], ecnt = g_binstart[b + 1] - elo;
            int nlo = lower_bound_dev(nidx, N_NODES, b);
            int ncnt = lower_bound_dev(nidx, N_NODES, b + 1) - nlo;
            cnts[b] = ((ecnt + 127) >> 7) + ((ncnt + 127) >> 7);
            info[b][0] = elo;
            info[b][1] = nlo;
        }
        __syncthreads();
        if (t == 0) {
            int run = 0;
            for (int i = 0; i < B_GR; i++) { starts[i] = run; run += cnts[i]; }
            g_ntiles = run;
        }
        __syncthreads();
        if (b < B_GR) {
            int elo = info[b][0], ecnt = g_binstart[b + 1] - elo;
            int nlo = info[b][1];
            int ncnt = lower_bound_dev(nidx, N_NODES, b + 1) - nlo;
            int et = (ecnt + 127) >> 7, nt = (ncnt + 127) >> 7;
            int idx = starts[b];
            for (int k = 0; k < et; k++)
                g_tiles[idx++] = make_int4(128, b, elo + k * 128, min(128, ecnt - k * 128));
            for (int k = 0; k < nt; k++)
                g_tiles[idx++] = make_int4(b, b, nlo + k * 128, min(128, ncnt - k * 128));
        }
    }
}

// ---------------- L3: main HMMA kernel ----------------
// 3-pass fp16 split for NODE tiles; 2-pass (Ah x Wh + Ah x Wl) for EDGE tiles.
// 256 threads, 8 warps = 2 m-groups (64 rows) x 4 n-groups (32 cols of this half).
__global__ void __launch_bounds__(256, 2) main_kernel(const float* __restrict__ node_attrs,
                                                      const float* __restrict__ edge_attrs,
                                                      const float* __restrict__ instr,
                                                      const float* __restrict__ w_node,
                                                      const float* __restrict__ w_rel) {
    extern __shared__ char smem[];
    const int tb = blockIdx.x >> 1;
    if (tb >= g_ntiles) return;
    const int half = blockIdx.x & 1;
    const int nofs = half * 128;
    const int4 ti = g_tiles[tb];
    const bool isEdge = (ti.x == 128);
    const bool threePass = !isEdge;   // nodes: full precision; edges: 2-pass
    const int tid = threadIdx.x;
    const int lane = tid & 31;
    const int wid = tid >> 5;
    const int mbase = (wid & 1) * 64;
    const int ngrp = wid >> 1;           // 0..3

    const uint32_t sb = smem_u32(smem);
    float* instr_s = (float*)(smem + OFF_INSTR);
    float* wvec_s = (float*)(smem + OFF_WVEC);
    float* red = (float*)(smem + OFF_RED);

    instr_s[tid] = instr[ti.y * D + tid];
    wvec_s[tid] = (isEdge ? w_rel : w_node)[tid];

    // A staging: 2 threads per row; thread covers 16 k-floats per chunk
    const int arow = tid >> 1;
    const int kseg = (tid & 1) * 16;
    const bool valid = arow < ti.w;
    const float* rowsrc = node_attrs;
    if (valid)
        rowsrc = isEdge ? edge_attrs + (size_t)g_eperm[ti.z + arow] * D
                        : node_attrs + (size_t)(ti.z + arow) * D;

    const __half* wh = g_Wsp + (size_t)ti.x * NCHUNK * W_CHUNK_ELEMS + (size_t)nofs * 32;

    float acc[4][4][4];
#pragma unroll
    for (int a = 0; a < 4; a++)
#pragma unroll
        for (int b = 0; b < 4; b++)
#pragma unroll
            for (int c = 0; c < 4; c++) acc[a][b][c] = 0.f;

    float4 va, vb, vc, vd;
#define ISSUE_W(c, buf)                                                             \
    do {                                                                            \
        uint32_t wbb = sb + OFF_W + (buf) * W_BUF_BYTES;                            \
        const __half* whc = wh + (size_t)(c) * W_CHUNK_ELEMS;                       \
        for (int s = tid; s < 512; s += 256) {                                      \
            int n_ = s >> 2, ks_ = s & 3;                                           \
            uint32_t d_ = wbb + n_ * 80 + ks_ * 16;                                 \
            size_t g_ = (size_t)n_ * 32 + ks_ * 8;                                  \
            cpasync16(d_, whc + g_);                                                \
            cpasync16(d_ + W_HL_BYTES, whc + WSP_HALF + g_);                        \
        }                                                                           \
        cp_commit();                                                                \
    } while (0)

#define LDG_A(c)                                                                    \
    do {                                                                            \
        if (valid) {                                                                \
            const float4* p_ = (const float4*)(rowsrc + (c) * KC + kseg);           \
            va = __ldg(p_); vb = __ldg(p_ + 1);                                     \
            vc = __ldg(p_ + 2); vd = __ldg(p_ + 3);                                 \
        } else {                                                                    \
            va = make_float4(0.f, 0.f, 0.f, 0.f);                                   \
            vb = va; vc = va; vd = va;                                              \
        }                                                                           \
    } while (0)

// Convert+store one float4: hi always; lo only for 3-pass (node) tiles.
#define STS_ONE(v, ab_, off)                                                        \
    do {                                                                            \
        __half2 hA = __floats2half2_rn((v).x, (v).y);                               \
        __half2 hB = __floats2half2_rn((v).z, (v).w);                               \
        uint2 u_;                                                                   \
        u_.x = *(uint32_t*)&hA; u_.y = *(uint32_t*)&hB;                             \
        *(uint2*)((ab_) + (off)) = u_;                                              \
        if (threePass) {                                                            \
            __half2 lA = __floats2half2_rn((v).x - __half2float(__low2half(hA)),    \
                                           (v).y - __half2float(__high2half(hA))); \
            __half2 lB = __floats2half2_rn((v).z - __half2float(__low2half(hB)),    \
                                           (v).w - __half2float(__high2half(hB))); \
            u_.x = *(uint32_t*)&lA; u_.y = *(uint32_t*)&lB;                         \
            *(uint2*)((ab_) + A_HL_BYTES + (off)) = u_;                             \
        }                                                                           \
    } while (0)

#define STS_A(buf)                                                                  \
    do {                                                                            \
        char* ab_ = smem + OFF_A + (buf) * A_BUF_BYTES + arow * 80 + kseg * 2;      \
        STS_ONE(va, ab_, 0);                                                        \
        STS_ONE(vb, ab_, 8);                                                        \
        STS_ONE(vc, ab_, 16);                                                       \
        STS_ONE(vd, ab_, 24);                                                       \
    } while (0)

    // prologue: issue chunk 0 and 1 (buffers 0, 1), stage A chunk 0
    ISSUE_W(0, 0);
    LDG_A(0);
    STS_A(0);
    ISSUE_W(1, 1);

#pragma unroll 1
    for (int c = 0; c < NCHUNK; c++) {
        if (c == NCHUNK - 1) cp_wait_all(); else cp_wait_1();
        __syncthreads();
        // Safe 2-deep prefetch: buffer (c+2)%3 was last read in iteration c-1;
        // the barrier above proves all warps are past it.
        if (c + 2 < NCHUNK) ISSUE_W(c + 2, (c + 2) % 3);
        if (c + 1 < NCHUNK) LDG_A(c + 1);
        const int abuf = c & 1;
        const uint32_t abase = sb + OFF_A + abuf * A_BUF_BYTES;
        const uint32_t wbase = sb + OFF_W + (c % 3) * W_BUF_BYTES;
        // ---- pass group 1: Ah x (Wh, Wl), acc revisit distance 16 ----
#pragma unroll
        for (int ks = 0; ks < 2; ks++) {
            const int k0 = ks * 16;
            uint32_t ah[4][4];
#pragma unroll
            for (int mi = 0; mi < 4; mi++) {
                uint32_t ra = abase + (mbase + mi * 16 + (lane & 15)) * 80 + k0 * 2 + ((lane >> 4) * 16);
                ldsm4(ah[mi], ra);
            }
            const uint32_t brow0 = wbase + (ngrp * 32 + ((lane >> 4) << 3) + (lane & 7)) * 80 +
                                   (((lane >> 3) & 1) * 16) + k0 * 2;
            const uint32_t brow1 = brow0 + 16 * 80;
            uint32_t b0h[4], b0l[4], b1h[4], b1l[4];
            ldsm4(b0h, brow0);
            ldsm4(b0l, brow0 + W_HL_BYTES);
            ldsm4(b1h, brow1);
            ldsm4(b1l, brow1 + W_HL_BYTES);
            // 16 mma on distinct accs (bh)
#pragma unroll
            for (int mi = 0; mi < 4; mi++) {
                mma16816(acc[mi][0], ah[mi], b0h[0], b0h[1]);
                mma16816(acc[mi][1], ah[mi], b0h[2], b0h[3]);
            }
#pragma unroll
            for (int mi = 0; mi < 4; mi++) {
                mma16816(acc[mi][2], ah[mi], b1h[0], b1h[1]);
                mma16816(acc[mi][3], ah[mi], b1h[2], b1h[3]);
            }
            // 16 mma revisiting each acc at distance 16 (bl)
#pragma unroll
            for (int mi = 0; mi < 4; mi++) {
                mma16816(acc[mi][0], ah[mi], b0l[0], b0l[1]);
                mma16816(acc[mi][1], ah[mi], b0l[2], b0l[3]);
            }
#pragma unroll
            for (int mi = 0; mi < 4; mi++) {
                mma16816(acc[mi][2], ah[mi], b1l[0], b1l[1]);
                mma16816(acc[mi][3], ah[mi], b1l[2], b1l[3]);
            }
        }
        // ---- pass group 2 (node tiles only): Al x Wh ----
        if (threePass) {
#pragma unroll
            for (int ks = 0; ks < 2; ks++) {
                const int k0 = ks * 16;
                uint32_t al[4][4];
#pragma unroll
                for (int mi = 0; mi < 4; mi++) {
                    uint32_t ra = abase + A_HL_BYTES + (mbase + mi * 16 + (lane & 15)) * 80 +
                                  k0 * 2 + ((lane >> 4) * 16);
                    ldsm4(al[mi], ra);
                }
                const uint32_t brow0 = wbase + (ngrp * 32 + ((lane >> 4) << 3) + (lane & 7)) * 80 +
                                       (((lane >> 3) & 1) * 16) + k0 * 2;
                const uint32_t brow1 = brow0 + 16 * 80;
                uint32_t b0h[4], b1h[4];
                ldsm4(b0h, brow0);
                ldsm4(b1h, brow1);
#pragma unroll
                for (int mi = 0; mi < 4; mi++) {
                    mma16816(acc[mi][0], al[mi], b0h[0], b0h[1]);
                    mma16816(acc[mi][1], al[mi], b0h[2], b0h[3]);
                }
#pragma unroll
                for (int mi = 0; mi < 4; mi++) {
                    mma16816(acc[mi][2], al[mi], b1h[0], b1h[1]);
                    mma16816(acc[mi][3], al[mi], b1h[2], b1h[3]);
                }
            }
        }
        if (c + 1 < NCHUNK) STS_A(abuf ^ 1);
    }

    // ---- epilogue: per-row partial over this half's 128 columns ----
#pragma unroll
    for (int mi = 0; mi < 4; mi++) {
        float pr0 = 0.f, pr1 = 0.f;
#pragma unroll
        for (int ni = 0; ni < 4; ni++) {
            int c0 = nofs + ngrp * 32 + (ni >> 1) * 16 + (ni & 1) * 8 + (lane & 3) * 2;
            float w0 = wvec_s[c0], w1 = wvec_s[c0 + 1];
            float i0 = instr_s[c0], i1 = instr_s[c0 + 1];
            pr0 += w0 * elu1(i0 * acc[mi][ni][0]) + w1 * elu1(i1 * acc[mi][ni][1]);
            pr1 += w0 * elu1(i0 * acc[mi][ni][2]) + w1 * elu1(i1 * acc[mi][ni][3]);
        }
        pr0 += __shfl_xor_sync(0xFFFFFFFFu, pr0, 1);
        pr0 += __shfl_xor_sync(0xFFFFFFFFu, pr0, 2);
        pr1 += __shfl_xor_sync(0xFFFFFFFFu, pr1, 1);
        pr1 += __shfl_xor_sync(0xFFFFFFFFu, pr1, 2);
        if ((lane & 3) == 0) {
            int row = mbase + mi * 16 + (lane >> 2);
            red[row * 4 + ngrp] = pr0;
            red[(row + 8) * 4 + ngrp] = pr1;
        }
    }
    __syncthreads();
    if (tid < 128 && tid < ti.w) {
        float v = red[tid * 4] + red[tid * 4 + 1] + red[tid * 4 + 2] + red[tid * 4 + 3];
        int gl = ti.z + tid;
        if (isEdge) atomicAdd(&g_rel_logits[g_edst[gl]], g_ecoef[gl] * v);
        else atomicAdd(&g_state_logits[gl], v);
    }
#undef ISSUE_W
#undef LDG_A
#undef STS_ONE
#undef STS_A
}

// ---------------- L4: segment softmax + combine ----------------
__global__ void __launch_bounds__(256) softmax_kernel(const int* __restrict__ nidx,
                                                      const float* __restrict__ rel_sim,
                                                      float* __restrict__ out) {
    const int b = blockIdx.x;
    const int t = threadIdx.x;
    __shared__ float sh[256];
    __shared__ int bounds[2];
    if (t == 0) {
        bounds[0] = lower_bound_dev(nidx, N_NODES, b);
        bounds[1] = lower_bound_dev(nidx, N_NODES, b + 1);
    }
    __syncthreads();
    const int lo = bounds[0], hi = bounds[1];
    if (hi <= lo) return;

    float m1 = -1e30f, m2 = -1e30f;
    for (int i = lo + t; i < hi; i += 256) {
        m1 = fmaxf(m1, g_state_logits[i]);
        m2 = fmaxf(m2, g_rel_logits[i]);
    }
    sh[t] = m1; __syncthreads();
    for (int o = 128; o > 0; o >>= 1) { if (t < o) sh[t] = fmaxf(sh[t], sh[t + o]); __syncthreads(); }
    m1 = sh[0]; __syncthreads();
    sh[t] = m2; __syncthreads();
    for (int o = 128; o > 0; o >>= 1) { if (t < o) sh[t] = fmaxf(sh[t], sh[t + o]); __syncthreads(); }
    m2 = sh[0]; __syncthreads();

    float s1 = 0.f, s2 = 0.f;
    for (int i = lo + t; i < hi; i += 256) {
        s1 += expf(g_state_logits[i] - m1);
        s2 += expf(g_rel_logits[i] - m2);
    }
    sh[t] = s1; __syncthreads();
    for (int o = 128; o > 0; o >>= 1) { if (t < o) sh[t] += sh[t + o]; __syncthreads(); }
    s1 = sh[0]; __syncthreads();
    sh[t] = s2; __syncthreads();
    for (int o = 128; o > 0; o >>= 1) { if (t < o) sh[t] += sh[t + o]; __syncthreads(); }
    s2 = sh[0]; __syncthreads();

    const float r = rel_sim[b];
    const float inv1 = 1.f / s1, inv2 = 1.f / s2;
    for (int i = lo + t; i < hi; i += 256) {
        float ns = expf(g_state_logits[i] - m1) * inv1;
        float nr = expf(g_rel_logits[i] - m2) * inv2;
        out[i] = r * nr + (1.f - r) * ns;
    }
}

extern "C" void kernel_launch(void* const* d_in, const int* in_sizes, int n_in,
                              void* d_out, int out_size) {
    const float* instr        = (const float*)d_in[0];
    const float* distribution = (const float*)d_in[1];
    const float* sim          = (const float*)d_in[2];
    const float* rel_sim      = (const float*)d_in[3];
    const float* node_attrs   = (const float*)d_in[4];
    const float* edge_attrs   = (const float*)d_in[5];
    const float* Wnp          = (const float*)d_in[6];
    const float* We           = (const float*)d_in[7];
    const float* w_node       = (const float*)d_in[8];
    const float* w_rel        = (const float*)d_in[9];
    const int*   node_indices = (const int*)d_in[10];
    const int*   edge_batch   = (const int*)d_in[11];
    const int*   ei           = (const int*)d_in[12];
    float* out = (float*)d_out;

    cudaFuncSetAttribute(main_kernel, cudaFuncAttributeMaxDynamicSharedMemorySize, SMEM_NEED);

    l0_kernel<<<NHB + ZBLK, 256>>>(edge_batch);
    scan_kernel<<<1, 128>>>();
    l2_kernel<<<NHB + WSBLK + 1, 256>>>(edge_batch, ei, ei + N_EDGES, distribution,
                                        Wnp, We, sim, node_indices);
    main_kernel<<<2 * MAX_TILES, 256, SMEM_NEED>>>(node_attrs, edge_attrs, instr,
                                                   w_node, w_rel);
    softmax_kernel<<<B_GR, 256>>>(node_indices, rel_sim, out);
}